// round 15
// baseline (speedup 1.0000x reference)
#include <cuda_runtime.h>
#include <cuda_bf16.h>
#include <cstdint>

#define BB   1024
#define AN   256
#define DD   256
#define HD   512
#define AD   512
#define KIN  1024
#define NRR  400
#define NF2  656
#define HUGEV 1e31f

// fp32 scratch
__device__ __align__(16) float g_Q0[BB * NF2], g_Q1[BB * NF2];
__device__ __align__(16) float g_S[BB * AN];
__device__ __align__(16) float g_br[NRR];
// bf16 hi/lo planes
__device__ __align__(16) __nv_bfloat16 g_Ah [BB * KIN],  g_Al [BB * KIN];
__device__ __align__(16) __nv_bfloat16 g_W1h[KIN * AD],  g_W1l[KIN * AD];
__device__ __align__(16) __nv_bfloat16 g_W2h[AD * AD],   g_W2l[AD * AD];
__device__ __align__(16) __nv_bfloat16 g_Rh [NRR * DD],  g_Rl [NRR * DD];
__device__ __align__(16) __nv_bfloat16 g_Xh [BB * AD],   g_Xl [BB * AD];
__device__ __align__(16) __nv_bfloat16 g_Wrh[AD * NRR],  g_Wrl[AD * NRR];

// ---------------------------------------------------------------------------
__device__ __forceinline__ uint32_t sh_addr(const void* p) {
    return (uint32_t)__cvta_generic_to_shared(p);
}
__device__ __forceinline__ void cp16(uint32_t dst, const void* src, int sz) {
    asm volatile("cp.async.cg.shared.global [%0], [%1], 16, %2;" :: "r"(dst), "l"(src), "r"(sz));
}
__device__ __forceinline__ void cp_commit() { asm volatile("cp.async.commit_group;"); }
template<int N> __device__ __forceinline__ void cp_wait() {
    asm volatile("cp.async.wait_group %0;" :: "n"(N));
}
__device__ __forceinline__ void ldsm_x4(uint32_t& r0, uint32_t& r1, uint32_t& r2, uint32_t& r3, uint32_t a) {
    asm volatile("ldmatrix.sync.aligned.m8n8.x4.shared.b16 {%0,%1,%2,%3}, [%4];"
                 : "=r"(r0), "=r"(r1), "=r"(r2), "=r"(r3) : "r"(a));
}
__device__ __forceinline__ void ldsm_x4_t(uint32_t& r0, uint32_t& r1, uint32_t& r2, uint32_t& r3, uint32_t a) {
    asm volatile("ldmatrix.sync.aligned.m8n8.x4.trans.shared.b16 {%0,%1,%2,%3}, [%4];"
                 : "=r"(r0), "=r"(r1), "=r"(r2), "=r"(r3) : "r"(a));
}
__device__ __forceinline__ void mma16816(float c[4], const uint32_t a[4], const uint32_t b[2]) {
    asm volatile(
        "mma.sync.aligned.m16n8k16.row.col.f32.bf16.bf16.f32 "
        "{%0,%1,%2,%3}, {%4,%5,%6,%7}, {%8,%9}, {%0,%1,%2,%3};"
        : "+f"(c[0]), "+f"(c[1]), "+f"(c[2]), "+f"(c[3])
        : "r"(a[0]), "r"(a[1]), "r"(a[2]), "r"(a[3]), "r"(b[0]), "r"(b[1]));
}
__device__ __forceinline__ uint32_t pack2(__nv_bfloat16 a, __nv_bfloat16 b) {
    __nv_bfloat162 p = __halves2bfloat162(a, b);
    return *reinterpret_cast<uint32_t*>(&p);
}
__device__ __forceinline__ void split1(float x, __nv_bfloat16& h, __nv_bfloat16& l) {
    h = __float2bfloat16(x);
    l = __float2bfloat16(x - __bfloat162float(h));
}
__device__ __forceinline__ void split4(float4 v, uint2& hw, uint2& lw) {
    float xs[4] = {v.x, v.y, v.z, v.w};
    __nv_bfloat16 h[4], l[4];
    #pragma unroll
    for (int i = 0; i < 4; i++) split1(xs[i], h[i], l[i]);
    hw = {pack2(h[0], h[1]), pack2(h[2], h[3])};
    lw = {pack2(l[0], l[1]), pack2(l[2], l[3])};
}

// ---------------------------------------------------------------------------
// 64x64 tile, BK=32, 256 threads, 3-stage (measured-best geometry).
// ---------------------------------------------------------------------------
#define MMA_TILE_KN(buf)                                                      \
    _Pragma("unroll")                                                         \
    for (int ks = 0; ks < 2; ks++) {                                          \
        uint32_t ah[4], al[4], bh[4][2], bl[4][2];                            \
        ldsm_x4(ah[0], ah[1], ah[2], ah[3], aAh[buf] + ks * 32);              \
        ldsm_x4(al[0], al[1], al[2], al[3], aAl[buf] + ks * 32);              \
        _Pragma("unroll")                                                     \
        for (int p = 0; p < 2; p++) {                                         \
            uint32_t off = (uint32_t)(ks * 16 * 144 + p * 32);                \
            ldsm_x4_t(bh[2*p][0], bh[2*p][1], bh[2*p+1][0], bh[2*p+1][1], aBh[buf] + off); \
            ldsm_x4_t(bl[2*p][0], bl[2*p][1], bl[2*p+1][0], bl[2*p+1][1], aBl[buf] + off); \
        }                                                                     \
        _Pragma("unroll")                                                     \
        for (int nt = 0; nt < 4; nt++) {                                      \
            mma16816(acc[nt], ah, bh[nt]);                                    \
            mma16816(acc[nt], ah, bl[nt]);                                    \
            mma16816(acc[nt], al, bh[nt]);                                    \
        }                                                                     \
    }

#define MMA_TILE_NK(buf)                                                      \
    _Pragma("unroll")                                                         \
    for (int ks = 0; ks < 2; ks++) {                                          \
        uint32_t ah[4], al[4], bh[4][2], bl[4][2];                            \
        ldsm_x4(ah[0], ah[1], ah[2], ah[3], aAh[buf] + ks * 32);              \
        ldsm_x4(al[0], al[1], al[2], al[3], aAl[buf] + ks * 32);              \
        _Pragma("unroll")                                                     \
        for (int p = 0; p < 2; p++) {                                         \
            uint32_t off = (uint32_t)(p * 16 * 80 + ks * 32);                 \
            ldsm_x4(bh[2*p][0], bh[2*p][1], bh[2*p+1][0], bh[2*p+1][1], aBh[buf] + off); \
            ldsm_x4(bl[2*p][0], bl[2*p][1], bl[2*p+1][0], bl[2*p+1][1], aBl[buf] + off); \
        }                                                                     \
        _Pragma("unroll")                                                     \
        for (int nt = 0; nt < 4; nt++) {                                      \
            mma16816(acc[nt], ah, bh[nt]);                                    \
            mma16816(acc[nt], ah, bl[nt]);                                    \
            mma16816(acc[nt], al, bh[nt]);                                    \
        }                                                                     \
    }

#define GEMM_IDS                                                              \
    int t = threadIdx.x;                                                      \
    int w = t >> 5, lane = t & 31;                                            \
    int wm = w >> 1, wn = w & 1;                                              \
    int gid = lane >> 2, tig = lane & 3;                                      \
    int lj = lane >> 3, lr = lane & 7;

#define LDSM_A_BASE(Ah, Al)                                                   \
    uint32_t aAh[3], aAl[3];                                                  \
    {   int a_row = wm * 16 + (lj & 1) * 8 + lr;                              \
        int a_kc  = (lj >> 1) * 8;                                            \
        _Pragma("unroll")                                                     \
        for (int s = 0; s < 3; s++) {                                         \
            aAh[s] = sh_addr(&Ah[s][a_row][a_kc]);                            \
            aAl[s] = sh_addr(&Al[s][a_row][a_kc]); } }

#define LDSM_BKN_BASE(Bh, Bl)                                                 \
    uint32_t aBh[3], aBl[3];                                                  \
    {   int b_kr = (lj & 1) * 8 + lr;                                         \
        int b_nc = wn * 32 + (lj >> 1) * 8;                                   \
        _Pragma("unroll")                                                     \
        for (int s = 0; s < 3; s++) {                                         \
            aBh[s] = sh_addr(&Bh[s][b_kr][b_nc]);                             \
            aBl[s] = sh_addr(&Bl[s][b_kr][b_nc]); } }

#define LDSM_BNK_BASE(Bh, Bl)                                                 \
    uint32_t aBh[3], aBl[3];                                                  \
    {   int b_nr = wn * 32 + (lj >> 1) * 8 + lr;                              \
        int b_kc = (lj & 1) * 8;                                              \
        _Pragma("unroll")                                                     \
        for (int s = 0; s < 3; s++) {                                         \
            aBh[s] = sh_addr(&Bh[s][b_nr][b_kc]);                             \
            aBl[s] = sh_addr(&Bl[s][b_nr][b_kc]); } }

#define PIPE_LOOP(NT, LOADER, MMA)                                            \
    LOADER(0, 0); cp_commit();                                                \
    LOADER(1, 1); cp_commit();                                                \
    int buf = 0;                                                              \
    for (int it = 0; it < NT; it++) {                                         \
        cp_wait<1>();                                                         \
        __syncthreads();                                                      \
        if (it + 2 < NT) { LOADER(it + 2, (it + 2) % 3); }                    \
        cp_commit();                                                          \
        MMA(buf);                                                             \
        buf = (buf + 1) % 3;                                                  \
    }

// ---------------------------------------------------------------------------
// k_prep: bf16 hi/lo planes + gathered concat A; tail blocks compute br.
// ---------------------------------------------------------------------------
#define U_A   (BB * KIN / 4)
#define U_W1  (KIN * AD / 4)
#define U_W2  (AD * AD / 4)
#define U_R   (NRR * DD / 4)
#define U_TOT (U_A + U_W1 + U_W2 + U_R)
#define UB    (U_TOT / 256)
#define BR_B  50

__global__ void __launch_bounds__(256)
k_prep(const int* __restrict__ e, const int* __restrict__ q,
       const float* __restrict__ hstate,
       const float* __restrict__ ent_emb,
       const float* __restrict__ rel_emb,
       const float* __restrict__ W1, const float* __restrict__ W2,
       const float* __restrict__ b2)
{
    if (blockIdx.x >= UB) {
        int warp = threadIdx.x >> 5, lane = threadIdx.x & 31;
        int r = (blockIdx.x - UB) * 8 + warp;
        if (r >= NRR) return;
        const float* rr = rel_emb + (size_t)r * DD;
        float s = 0.f;
        #pragma unroll
        for (int j = lane; j < DD; j += 32) s = fmaf(b2[j], rr[j], s);
        #pragma unroll
        for (int o = 16; o > 0; o >>= 1) s += __shfl_xor_sync(0xFFFFFFFFu, s, o);
        if (lane == 0) g_br[r] = s;
        return;
    }

    int u = blockIdx.x * 256 + threadIdx.x;
    float4 v;
    __nv_bfloat16 *ph, *pl;
    size_t off;
    if (u < U_A) {
        int b  = u >> 8;
        int kc = (u & 255) * 4;
        const float* p = (kc < DD) ? ent_emb + (size_t)e[b] * DD + kc
                       : (kc < DD + HD) ? hstate + (size_t)b * HD + (kc - DD)
                       : rel_emb + (size_t)q[b] * DD + (kc - DD - HD);
        v = *(const float4*)p;
        off = (size_t)u * 4; ph = g_Ah; pl = g_Al;
    } else if (u < U_A + U_W1) {
        size_t i = (size_t)(u - U_A) * 4;
        v = *(const float4*)&W1[i];
        off = i; ph = g_W1h; pl = g_W1l;
    } else if (u < U_A + U_W1 + U_W2) {
        size_t i = (size_t)(u - U_A - U_W1) * 4;
        v = *(const float4*)&W2[i];
        off = i; ph = g_W2h; pl = g_W2l;
    } else {
        size_t i = (size_t)(u - U_A - U_W1 - U_W2) * 4;
        v = *(const float4*)&rel_emb[i];
        off = i; ph = g_Rh; pl = g_Rl;
    }
    uint2 hw, lw;
    split4(v, hw, lw);
    *(uint2*)&ph[off] = hw;
    *(uint2*)&pl[off] = lw;
}

// ---------------------------------------------------------------------------
// Combined GEMM1 (full K) + Wr in one launch.
// z == 0: X = relu(A @ W1 + b1) -> bf16 hi/lo   (grid x=8, y=16)
// z == 1: Wr = W2[:, :256] @ rel_emb^T          (x<7, y<8 active)
// ---------------------------------------------------------------------------
typedef __nv_bfloat16 (*SmA3)[64][40];
typedef __nv_bfloat16 (*SmB3)[32][72];

__global__ void __launch_bounds__(256)
k_wrg1(const float* __restrict__ b1)
{
    __shared__ __nv_bfloat16 SB[30720];

    GEMM_IDS;

    if (blockIdx.z == 0) {
        SmA3 Ah = (SmA3)(SB);
        SmA3 Al = (SmA3)(SB + 7680);
        SmB3 Bh = (SmB3)(SB + 15360);
        SmB3 Bl = (SmB3)(SB + 22272);

        int m0 = blockIdx.y * 64, n0 = blockIdx.x * 64;

        LDSM_A_BASE(Ah, Al);
        LDSM_BKN_BASE(Bh, Bl);

        int ar = t >> 2, ac = (t & 3) * 8;
        int br = t >> 3, bc = (t & 7) * 8;
        const __nv_bfloat16* gAh = g_Ah + (size_t)(m0 + ar) * KIN + ac;
        const __nv_bfloat16* gAl = g_Al + (size_t)(m0 + ar) * KIN + ac;
        uint32_t dAh[3], dAl[3], dBh[3], dBl[3];
        #pragma unroll
        for (int s = 0; s < 3; s++) {
            dAh[s] = sh_addr(&Ah[s][ar][ac]); dAl[s] = sh_addr(&Al[s][ar][ac]);
            dBh[s] = sh_addr(&Bh[s][br][bc]); dBl[s] = sh_addr(&Bl[s][br][bc]);
        }

        float acc[4][4] = {};
        const int NT = KIN / 32;

        #define LOAD1(it, s) {                                                \
            int k0 = (it) * 32;                                               \
            cp16(dAh[s], gAh + k0, 16);                                       \
            cp16(dAl[s], gAl + k0, 16);                                       \
            cp16(dBh[s], g_W1h + (size_t)(k0 + br) * AD + n0 + bc, 16);       \
            cp16(dBl[s], g_W1l + (size_t)(k0 + br) * AD + n0 + bc, 16); }

        PIPE_LOOP(NT, LOAD1, MMA_TILE_KN);
        #undef LOAD1

        #pragma unroll
        for (int nt = 0; nt < 4; nt++) {
            int r0 = m0 + wm * 16 + gid;
            int c0 = n0 + wn * 32 + nt * 8 + 2 * tig;
            float bb0 = b1[c0], bb1 = b1[c0 + 1];
            float v00 = fmaxf(acc[nt][0] + bb0, 0.f), v01 = fmaxf(acc[nt][1] + bb1, 0.f);
            float v10 = fmaxf(acc[nt][2] + bb0, 0.f), v11 = fmaxf(acc[nt][3] + bb1, 0.f);
            __nv_bfloat16 h0, l0, h1, l1;
            split1(v00, h0, l0); split1(v01, h1, l1);
            *(uint32_t*)&g_Xh[(size_t)r0 * AD + c0] = pack2(h0, h1);
            *(uint32_t*)&g_Xl[(size_t)r0 * AD + c0] = pack2(l0, l1);
            split1(v10, h0, l0); split1(v11, h1, l1);
            *(uint32_t*)&g_Xh[(size_t)(r0 + 8) * AD + c0] = pack2(h0, h1);
            *(uint32_t*)&g_Xl[(size_t)(r0 + 8) * AD + c0] = pack2(l0, l1);
        }
    } else {
        if (blockIdx.x >= 7 || blockIdx.y >= 8) return;
        SmA3 Ah = (SmA3)(SB);
        SmA3 Al = (SmA3)(SB + 7680);
        SmA3 Bh = (SmA3)(SB + 15360);
        SmA3 Bl = (SmA3)(SB + 23040);

        int m0 = blockIdx.y * 64, n0 = blockIdx.x * 64;

        LDSM_A_BASE(Ah, Al);
        LDSM_BNK_BASE(Bh, Bl);

        int ar = t >> 2, ac = (t & 3) * 8;
        int rr = n0 + ar;
        int bsz = (rr < NRR) ? 16 : 0;
        const __nv_bfloat16* gRh = g_Rh + (size_t)(rr < NRR ? rr : 0) * DD + ac;
        const __nv_bfloat16* gRl = g_Rl + (size_t)(rr < NRR ? rr : 0) * DD + ac;
        uint32_t dAh[3], dAl[3], dBh[3], dBl[3];
        #pragma unroll
        for (int s = 0; s < 3; s++) {
            dAh[s] = sh_addr(&Ah[s][ar][ac]); dAl[s] = sh_addr(&Al[s][ar][ac]);
            dBh[s] = sh_addr(&Bh[s][ar][ac]); dBl[s] = sh_addr(&Bl[s][ar][ac]);
        }

        float acc[4][4] = {};
        const int NT = DD / 32;

        #define LOADW(it, s) {                                                \
            int k0 = (it) * 32;                                               \
            cp16(dAh[s], g_W2h + (size_t)(m0 + ar) * AD + k0 + ac, 16);       \
            cp16(dAl[s], g_W2l + (size_t)(m0 + ar) * AD + k0 + ac, 16);       \
            cp16(dBh[s], gRh + k0, bsz);                                      \
            cp16(dBl[s], gRl + k0, bsz); }

        PIPE_LOOP(NT, LOADW, MMA_TILE_NK);
        #undef LOADW

        #pragma unroll
        for (int nt = 0; nt < 4; nt++) {
            int r0 = m0 + wm * 16 + gid;
            int c0 = n0 + wn * 32 + nt * 8 + 2 * tig;
            if (c0 < NRR) {
                __nv_bfloat16 h0, l0, h1, l1;
                split1(acc[nt][0], h0, l0); split1(acc[nt][1], h1, l1);
                *(uint32_t*)&g_Wrh[(size_t)r0 * NRR + c0] = pack2(h0, h1);
                *(uint32_t*)&g_Wrl[(size_t)r0 * NRR + c0] = pack2(l0, l1);
                split1(acc[nt][2], h0, l0); split1(acc[nt][3], h1, l1);
                *(uint32_t*)&g_Wrh[(size_t)(r0 + 8) * NRR + c0] = pack2(h0, h1);
                *(uint32_t*)&g_Wrl[(size_t)(r0 + 8) * NRR + c0] = pack2(l0, l1);
            }
        }
    }
}

// ---------------------------------------------------------------------------
// GEMM2 split-K2: Q[z] = X[:, z*256:+256] @ [W2[:,256:512] | Wr].
// ---------------------------------------------------------------------------
__global__ void __launch_bounds__(256)
k_gemm2f()
{
    __shared__ __nv_bfloat16 Ah[3][64][40], Al[3][64][40];
    __shared__ __nv_bfloat16 Bh[3][32][72], Bl[3][32][72];

    GEMM_IDS;
    int m0 = blockIdx.y * 64, n0 = blockIdx.x * 64;
    int koff = blockIdx.z * (AD / 2);
    float* Q = blockIdx.z ? g_Q1 : g_Q0;

    LDSM_A_BASE(Ah, Al);
    LDSM_BKN_BASE(Bh, Bl);

    int ar = t >> 2, ac = (t & 3) * 8;
    int br = t >> 3, bc = (t & 7) * 8;
    int bcol = n0 + bc;
    const __nv_bfloat16* gAh = g_Xh + (size_t)(m0 + ar) * AD + koff + ac;
    const __nv_bfloat16* gAl = g_Xl + (size_t)(m0 + ar) * AD + koff + ac;
    uint32_t dAh[3], dAl[3], dBh[3], dBl[3];
    #pragma unroll
    for (int s = 0; s < 3; s++) {
        dAh[s] = sh_addr(&Ah[s][ar][ac]); dAl[s] = sh_addr(&Al[s][ar][ac]);
        dBh[s] = sh_addr(&Bh[s][br][bc]); dBl[s] = sh_addr(&Bl[s][br][bc]);
    }

    float acc[4][4] = {};
    const int NT = (AD / 2) / 32;

    #define LOAD2(it, s) {                                                    \
        int k0 = (it) * 32;                                                   \
        cp16(dAh[s], gAh + k0, 16);                                           \
        cp16(dAl[s], gAl + k0, 16);                                           \
        int kk = koff + k0 + br;                                              \
        const __nv_bfloat16 *sh_, *sl_; int sz_ = 16;                         \
        if (bcol < DD)       { sh_ = g_W2h + (size_t)kk * AD + DD + bcol;     \
                               sl_ = g_W2l + (size_t)kk * AD + DD + bcol; }   \
        else if (bcol < NF2) { sh_ = g_Wrh + (size_t)kk * NRR + (bcol - DD);  \
                               sl_ = g_Wrl + (size_t)kk * NRR + (bcol - DD); }\
        else                 { sh_ = g_W2h; sl_ = g_W2l; sz_ = 0; }           \
        cp16(dBh[s], sh_, sz_);                                               \
        cp16(dBl[s], sl_, sz_); }

    PIPE_LOOP(NT, LOAD2, MMA_TILE_KN);
    #undef LOAD2

    #pragma unroll
    for (int nt = 0; nt < 4; nt++) {
        int r0 = m0 + wm * 16 + gid;
        int c0 = n0 + wn * 32 + nt * 8 + 2 * tig;
        if (c0 < NF2) {
            *(float2*)&Q[(size_t)r0 * NF2 + c0]       = {acc[nt][0], acc[nt][1]};
            *(float2*)&Q[(size_t)(r0 + 8) * NF2 + c0] = {acc[nt][2], acc[nt][3]};
        }
    }
}

// ---------------------------------------------------------------------------
// k_gather (cp.async staged + mask-skip): grid (2, 1024), 256 threads.
// 128 actions/block in 8 stages of 16 rows, double-buffered smem; masked
// rows get sz=0 zero-fill (no global traffic).
// ---------------------------------------------------------------------------
#define GR 16
__global__ void __launch_bounds__(256)
k_gather(const int* __restrict__ e_space,
         const float* __restrict__ mask,
         const float* __restrict__ ent_emb,
         const float* __restrict__ b2)
{
    int b = blockIdx.y;
    int t = threadIdx.x;
    int warp = t >> 5, lane = t & 31;

    __shared__ __align__(16) float x2b[DD];
    __shared__ __align__(16) float stg[2][GR][DD];
    __shared__ int sidx[128];
    __shared__ float smask[128];

    const size_t qb = (size_t)b * NF2;
    x2b[t] = g_Q0[qb + t] + g_Q1[qb + t] + b2[DD + t];
    int abase = blockIdx.x * 128;
    const int base = b * AN;
    if (t < 128) {
        sidx[t]  = e_space[base + abase + t];
        smask[t] = mask[base + abase + t];
    }
    __syncthreads();

    const float4* xp = reinterpret_cast<const float4*>(x2b);
    float4 xv0 = xp[lane * 2 + 0];
    float4 xv1 = xp[lane * 2 + 1];

    int lrow = t >> 4;
    int lch  = t & 15;
    uint32_t sdst[2] = { sh_addr(&stg[0][lrow][lch * 4]),
                         sh_addr(&stg[1][lrow][lch * 4]) };

    #define GLOAD(s, bf) {                                                    \
        int arow = (s) * GR + lrow;                                           \
        int sz = (smask[arow] != 0.0f) ? 16 : 0;                              \
        const float* src = ent_emb + (size_t)sidx[arow] * DD + lch * 4;       \
        _Pragma("unroll")                                                     \
        for (int j = 0; j < 4; j++)                                           \
            cp16(sdst[bf] + (uint32_t)(j * 256), src + j * 64, sz); }

    GLOAD(0, 0); cp_commit();
    int bf = 0;
    #pragma unroll 1
    for (int s = 0; s < 8; s++) {
        if (s + 1 < 8) { GLOAD(s + 1, bf ^ 1); }
        cp_commit();
        cp_wait<1>();
        __syncthreads();
        #pragma unroll
        for (int r2 = 0; r2 < 2; r2++) {
            int row = warp * 2 + r2;
            const float4* rp = reinterpret_cast<const float4*>(&stg[bf][row][0]);
            float4 v0 = rp[lane * 2 + 0];
            float4 v1 = rp[lane * 2 + 1];
            float sv = v0.x * xv0.x + v0.y * xv0.y + v0.z * xv0.z + v0.w * xv0.w
                     + v1.x * xv1.x + v1.y * xv1.y + v1.z * xv1.z + v1.w * xv1.w;
            #pragma unroll
            for (int o = 16; o > 0; o >>= 1) sv += __shfl_xor_sync(0xFFFFFFFFu, sv, o);
            if (lane == 0) g_S[base + abase + s * GR + row] = sv;
        }
        __syncthreads();
        bf ^= 1;
    }
    #undef GLOAD
}

// ---------------------------------------------------------------------------
// k_softmax: relation term + mask, softmax, entropy.  Grid 1024, 256 thr.
// ---------------------------------------------------------------------------
__global__ void __launch_bounds__(256)
k_softmax(const int*   __restrict__ r_space,
          const float* __restrict__ mask,
          float* __restrict__ dist,
          float* __restrict__ entropy)
{
    int b = blockIdx.x;
    int t = threadIdx.x;
    int warp = t >> 5, lane = t & 31;

    __shared__ float rp[NRR];
    __shared__ float red[8];

    const size_t qb = (size_t)b * NF2;
    for (int i = t; i < NRR; i += 256)
        rp[i] = g_Q0[qb + DD + i] + g_Q1[qb + DD + i] + g_br[i];
    __syncthreads();

    int ir = r_space[b * AN + t];
    float m = mask[b * AN + t];
    float s = g_S[b * AN + t] + rp[ir] - (1.0f - m) * HUGEV;

    float mx = s;
    #pragma unroll
    for (int o = 16; o > 0; o >>= 1) mx = fmaxf(mx, __shfl_xor_sync(0xFFFFFFFFu, mx, o));
    if (lane == 0) red[warp] = mx;
    __syncthreads();
    if (t < 8) {
        float v = red[t];
        #pragma unroll
        for (int o = 4; o > 0; o >>= 1) v = fmaxf(v, __shfl_xor_sync(0xFFu, v, o));
        if (t == 0) red[0] = v;
    }
    __syncthreads();
    mx = red[0];

    float ex = expf(s - mx);

    float sm = ex;
    #pragma unroll
    for (int o = 16; o > 0; o >>= 1) sm += __shfl_xor_sync(0xFFFFFFFFu, sm, o);
    __syncthreads();
    if (lane == 0) red[warp] = sm;
    __syncthreads();
    if (t < 8) {
        float v = red[t];
        #pragma unroll
        for (int o = 4; o > 0; o >>= 1) v += __shfl_xor_sync(0xFFu, v, o);
        if (t == 0) red[0] = v;
    }
    __syncthreads();
    float total = red[0];

    float p = ex / total;
    dist[(size_t)b * AN + t] = p;

    float term = p * logf(fmaxf(p, 1e-20f));
    float es = term;
    #pragma unroll
    for (int o = 16; o > 0; o >>= 1) es += __shfl_xor_sync(0xFFFFFFFFu, es, o);
    __syncthreads();
    if (lane == 0) red[warp] = es;
    __syncthreads();
    if (t < 8) {
        float v = red[t];
        #pragma unroll
        for (int o = 4; o > 0; o >>= 1) v += __shfl_xor_sync(0xFFu, v, o);
        if (t == 0) entropy[b] = -v;
    }
}

// ---------------------------------------------------------------------------
extern "C" void kernel_launch(void* const* d_in, const int* in_sizes, int n_in,
                              void* d_out, int out_size)
{
    const int*   e        = (const int*)  d_in[0];
    const int*   q        = (const int*)  d_in[1];
    const float* hstate   = (const float*)d_in[2];
    const int*   r_space  = (const int*)  d_in[3];
    const int*   e_space  = (const int*)  d_in[4];
    const float* amask    = (const float*)d_in[5];
    const float* ent_emb  = (const float*)d_in[6];
    const float* rel_emb  = (const float*)d_in[7];
    const float* W1       = (const float*)d_in[8];
    const float* b1       = (const float*)d_in[9];
    const float* W2       = (const float*)d_in[10];
    const float* b2       = (const float*)d_in[11];

    float* dist    = (float*)d_out;
    float* entropy = (float*)d_out + (size_t)BB * AN;

    k_prep<<<UB + BR_B, 256>>>(e, q, hstate, ent_emb, rel_emb, W1, W2, b2);

    dim3 g1(8, 16, 2);                          // z=0 gemm1, z=1 wr
    k_wrg1<<<g1, 256>>>(b1);

    dim3 g2((NF2 + 63) / 64, BB / 64, 2);       // (11, 16, 2) = 352
    k_gemm2f<<<g2, 256>>>();

    dim3 gg(2, BB);                             // (2, 1024)
    k_gather<<<gg, 256>>>(e_space, amask, ent_emb, b2);

    k_softmax<<<BB, 256>>>(r_space, amask, dist, entropy);
}

// round 16
// speedup vs baseline: 1.0284x; 1.0284x over previous
#include <cuda_runtime.h>
#include <cuda_bf16.h>
#include <cstdint>

#define BB   1024
#define AN   256
#define DD   256
#define HD   512
#define AD   512
#define KIN  1024
#define NRR  400
#define NF2  656
#define HUGEV 1e31f

// fp32 scratch
__device__ __align__(16) float g_Q0[BB * NF2], g_Q1[BB * NF2];
__device__ __align__(16) float g_S[BB * AN];
__device__ __align__(16) float g_br[NRR];
// bf16 hi/lo planes
__device__ __align__(16) __nv_bfloat16 g_Ah [BB * KIN],  g_Al [BB * KIN];
__device__ __align__(16) __nv_bfloat16 g_W1h[KIN * AD],  g_W1l[KIN * AD];
__device__ __align__(16) __nv_bfloat16 g_W2h[AD * AD],   g_W2l[AD * AD];
__device__ __align__(16) __nv_bfloat16 g_Rh [NRR * DD],  g_Rl [NRR * DD];
__device__ __align__(16) __nv_bfloat16 g_Xh [BB * AD],   g_Xl [BB * AD];
__device__ __align__(16) __nv_bfloat16 g_Wrh[AD * NRR],  g_Wrl[AD * NRR];

// ---------------------------------------------------------------------------
__device__ __forceinline__ uint32_t sh_addr(const void* p) {
    return (uint32_t)__cvta_generic_to_shared(p);
}
__device__ __forceinline__ void cp16(uint32_t dst, const void* src, int sz) {
    asm volatile("cp.async.cg.shared.global [%0], [%1], 16, %2;" :: "r"(dst), "l"(src), "r"(sz));
}
__device__ __forceinline__ void cp_commit() { asm volatile("cp.async.commit_group;"); }
template<int N> __device__ __forceinline__ void cp_wait() {
    asm volatile("cp.async.wait_group %0;" :: "n"(N));
}
__device__ __forceinline__ void ldsm_x4(uint32_t& r0, uint32_t& r1, uint32_t& r2, uint32_t& r3, uint32_t a) {
    asm volatile("ldmatrix.sync.aligned.m8n8.x4.shared.b16 {%0,%1,%2,%3}, [%4];"
                 : "=r"(r0), "=r"(r1), "=r"(r2), "=r"(r3) : "r"(a));
}
__device__ __forceinline__ void ldsm_x4_t(uint32_t& r0, uint32_t& r1, uint32_t& r2, uint32_t& r3, uint32_t a) {
    asm volatile("ldmatrix.sync.aligned.m8n8.x4.trans.shared.b16 {%0,%1,%2,%3}, [%4];"
                 : "=r"(r0), "=r"(r1), "=r"(r2), "=r"(r3) : "r"(a));
}
__device__ __forceinline__ void mma16816(float c[4], const uint32_t a[4], const uint32_t b[2]) {
    asm volatile(
        "mma.sync.aligned.m16n8k16.row.col.f32.bf16.bf16.f32 "
        "{%0,%1,%2,%3}, {%4,%5,%6,%7}, {%8,%9}, {%0,%1,%2,%3};"
        : "+f"(c[0]), "+f"(c[1]), "+f"(c[2]), "+f"(c[3])
        : "r"(a[0]), "r"(a[1]), "r"(a[2]), "r"(a[3]), "r"(b[0]), "r"(b[1]));
}
__device__ __forceinline__ uint32_t pack2(__nv_bfloat16 a, __nv_bfloat16 b) {
    __nv_bfloat162 p = __halves2bfloat162(a, b);
    return *reinterpret_cast<uint32_t*>(&p);
}
__device__ __forceinline__ void split1(float x, __nv_bfloat16& h, __nv_bfloat16& l) {
    h = __float2bfloat16(x);
    l = __float2bfloat16(x - __bfloat162float(h));
}
__device__ __forceinline__ void split4(float4 v, uint2& hw, uint2& lw) {
    float xs[4] = {v.x, v.y, v.z, v.w};
    __nv_bfloat16 h[4], l[4];
    #pragma unroll
    for (int i = 0; i < 4; i++) split1(xs[i], h[i], l[i]);
    hw = {pack2(h[0], h[1]), pack2(h[2], h[3])};
    lw = {pack2(l[0], l[1]), pack2(l[2], l[3])};
}

// ---------------------------------------------------------------------------
// 64x64 tile, BK=32, 256 threads, 3-stage (measured-best geometry).
// ---------------------------------------------------------------------------
#define MMA_TILE_KN(buf)                                                      \
    _Pragma("unroll")                                                         \
    for (int ks = 0; ks < 2; ks++) {                                          \
        uint32_t ah[4], al[4], bh[4][2], bl[4][2];                            \
        ldsm_x4(ah[0], ah[1], ah[2], ah[3], aAh[buf] + ks * 32);              \
        ldsm_x4(al[0], al[1], al[2], al[3], aAl[buf] + ks * 32);              \
        _Pragma("unroll")                                                     \
        for (int p = 0; p < 2; p++) {                                         \
            uint32_t off = (uint32_t)(ks * 16 * 144 + p * 32);                \
            ldsm_x4_t(bh[2*p][0], bh[2*p][1], bh[2*p+1][0], bh[2*p+1][1], aBh[buf] + off); \
            ldsm_x4_t(bl[2*p][0], bl[2*p][1], bl[2*p+1][0], bl[2*p+1][1], aBl[buf] + off); \
        }                                                                     \
        _Pragma("unroll")                                                     \
        for (int nt = 0; nt < 4; nt++) {                                      \
            mma16816(acc[nt], ah, bh[nt]);                                    \
            mma16816(acc[nt], ah, bl[nt]);                                    \
            mma16816(acc[nt], al, bh[nt]);                                    \
        }                                                                     \
    }

#define MMA_TILE_NK(buf)                                                      \
    _Pragma("unroll")                                                         \
    for (int ks = 0; ks < 2; ks++) {                                          \
        uint32_t ah[4], al[4], bh[4][2], bl[4][2];                            \
        ldsm_x4(ah[0], ah[1], ah[2], ah[3], aAh[buf] + ks * 32);              \
        ldsm_x4(al[0], al[1], al[2], al[3], aAl[buf] + ks * 32);              \
        _Pragma("unroll")                                                     \
        for (int p = 0; p < 2; p++) {                                         \
            uint32_t off = (uint32_t)(p * 16 * 80 + ks * 32);                 \
            ldsm_x4(bh[2*p][0], bh[2*p][1], bh[2*p+1][0], bh[2*p+1][1], aBh[buf] + off); \
            ldsm_x4(bl[2*p][0], bl[2*p][1], bl[2*p+1][0], bl[2*p+1][1], aBl[buf] + off); \
        }                                                                     \
        _Pragma("unroll")                                                     \
        for (int nt = 0; nt < 4; nt++) {                                      \
            mma16816(acc[nt], ah, bh[nt]);                                    \
            mma16816(acc[nt], ah, bl[nt]);                                    \
            mma16816(acc[nt], al, bh[nt]);                                    \
        }                                                                     \
    }

#define GEMM_IDS                                                              \
    int t = threadIdx.x;                                                      \
    int w = t >> 5, lane = t & 31;                                            \
    int wm = w >> 1, wn = w & 1;                                              \
    int gid = lane >> 2, tig = lane & 3;                                      \
    int lj = lane >> 3, lr = lane & 7;

#define LDSM_A_BASE(Ah, Al)                                                   \
    uint32_t aAh[3], aAl[3];                                                  \
    {   int a_row = wm * 16 + (lj & 1) * 8 + lr;                              \
        int a_kc  = (lj >> 1) * 8;                                            \
        _Pragma("unroll")                                                     \
        for (int s = 0; s < 3; s++) {                                         \
            aAh[s] = sh_addr(&Ah[s][a_row][a_kc]);                            \
            aAl[s] = sh_addr(&Al[s][a_row][a_kc]); } }

#define LDSM_BKN_BASE(Bh, Bl)                                                 \
    uint32_t aBh[3], aBl[3];                                                  \
    {   int b_kr = (lj & 1) * 8 + lr;                                         \
        int b_nc = wn * 32 + (lj >> 1) * 8;                                   \
        _Pragma("unroll")                                                     \
        for (int s = 0; s < 3; s++) {                                         \
            aBh[s] = sh_addr(&Bh[s][b_kr][b_nc]);                             \
            aBl[s] = sh_addr(&Bl[s][b_kr][b_nc]); } }

#define LDSM_BNK_BASE(Bh, Bl)                                                 \
    uint32_t aBh[3], aBl[3];                                                  \
    {   int b_nr = wn * 32 + (lj >> 1) * 8 + lr;                              \
        int b_kc = (lj & 1) * 8;                                              \
        _Pragma("unroll")                                                     \
        for (int s = 0; s < 3; s++) {                                         \
            aBh[s] = sh_addr(&Bh[s][b_nr][b_kc]);                             \
            aBl[s] = sh_addr(&Bl[s][b_nr][b_kc]); } }

#define PIPE_LOOP(NT, LOADER, MMA)                                            \
    LOADER(0, 0); cp_commit();                                                \
    LOADER(1, 1); cp_commit();                                                \
    int buf = 0;                                                              \
    for (int it = 0; it < NT; it++) {                                         \
        cp_wait<1>();                                                         \
        __syncthreads();                                                      \
        if (it + 2 < NT) { LOADER(it + 2, (it + 2) % 3); }                    \
        cp_commit();                                                          \
        MMA(buf);                                                             \
        buf = (buf + 1) % 3;                                                  \
    }

// ---------------------------------------------------------------------------
// k_prep: bf16 hi/lo planes + gathered concat A; tail blocks compute br.
// ---------------------------------------------------------------------------
#define U_A   (BB * KIN / 4)
#define U_W1  (KIN * AD / 4)
#define U_W2  (AD * AD / 4)
#define U_R   (NRR * DD / 4)
#define U_TOT (U_A + U_W1 + U_W2 + U_R)
#define UB    (U_TOT / 256)
#define BR_B  50

__global__ void __launch_bounds__(256)
k_prep(const int* __restrict__ e, const int* __restrict__ q,
       const float* __restrict__ hstate,
       const float* __restrict__ ent_emb,
       const float* __restrict__ rel_emb,
       const float* __restrict__ W1, const float* __restrict__ W2,
       const float* __restrict__ b2)
{
    if (blockIdx.x >= UB) {
        int warp = threadIdx.x >> 5, lane = threadIdx.x & 31;
        int r = (blockIdx.x - UB) * 8 + warp;
        if (r >= NRR) return;
        const float* rr = rel_emb + (size_t)r * DD;
        float s = 0.f;
        #pragma unroll
        for (int j = lane; j < DD; j += 32) s = fmaf(b2[j], rr[j], s);
        #pragma unroll
        for (int o = 16; o > 0; o >>= 1) s += __shfl_xor_sync(0xFFFFFFFFu, s, o);
        if (lane == 0) g_br[r] = s;
        return;
    }

    int u = blockIdx.x * 256 + threadIdx.x;
    float4 v;
    __nv_bfloat16 *ph, *pl;
    size_t off;
    if (u < U_A) {
        int b  = u >> 8;
        int kc = (u & 255) * 4;
        const float* p = (kc < DD) ? ent_emb + (size_t)e[b] * DD + kc
                       : (kc < DD + HD) ? hstate + (size_t)b * HD + (kc - DD)
                       : rel_emb + (size_t)q[b] * DD + (kc - DD - HD);
        v = *(const float4*)p;
        off = (size_t)u * 4; ph = g_Ah; pl = g_Al;
    } else if (u < U_A + U_W1) {
        size_t i = (size_t)(u - U_A) * 4;
        v = *(const float4*)&W1[i];
        off = i; ph = g_W1h; pl = g_W1l;
    } else if (u < U_A + U_W1 + U_W2) {
        size_t i = (size_t)(u - U_A - U_W1) * 4;
        v = *(const float4*)&W2[i];
        off = i; ph = g_W2h; pl = g_W2l;
    } else {
        size_t i = (size_t)(u - U_A - U_W1 - U_W2) * 4;
        v = *(const float4*)&rel_emb[i];
        off = i; ph = g_Rh; pl = g_Rl;
    }
    uint2 hw, lw;
    split4(v, hw, lw);
    *(uint2*)&ph[off] = hw;
    *(uint2*)&pl[off] = lw;
}

// ---------------------------------------------------------------------------
// Combined GEMM1 (full K) + Wr in one launch.
// z == 0: X = relu(A @ W1 + b1) -> bf16 hi/lo   (grid x=8, y=16)
// z == 1: Wr = W2[:, :256] @ rel_emb^T          (x<7, y<8 active)
// ---------------------------------------------------------------------------
typedef __nv_bfloat16 (*SmA3)[64][40];
typedef __nv_bfloat16 (*SmB3)[32][72];

__global__ void __launch_bounds__(256)
k_wrg1(const float* __restrict__ b1)
{
    __shared__ __nv_bfloat16 SB[30720];

    GEMM_IDS;

    if (blockIdx.z == 0) {
        SmA3 Ah = (SmA3)(SB);
        SmA3 Al = (SmA3)(SB + 7680);
        SmB3 Bh = (SmB3)(SB + 15360);
        SmB3 Bl = (SmB3)(SB + 22272);

        int m0 = blockIdx.y * 64, n0 = blockIdx.x * 64;

        LDSM_A_BASE(Ah, Al);
        LDSM_BKN_BASE(Bh, Bl);

        int ar = t >> 2, ac = (t & 3) * 8;
        int br = t >> 3, bc = (t & 7) * 8;
        const __nv_bfloat16* gAh = g_Ah + (size_t)(m0 + ar) * KIN + ac;
        const __nv_bfloat16* gAl = g_Al + (size_t)(m0 + ar) * KIN + ac;
        uint32_t dAh[3], dAl[3], dBh[3], dBl[3];
        #pragma unroll
        for (int s = 0; s < 3; s++) {
            dAh[s] = sh_addr(&Ah[s][ar][ac]); dAl[s] = sh_addr(&Al[s][ar][ac]);
            dBh[s] = sh_addr(&Bh[s][br][bc]); dBl[s] = sh_addr(&Bl[s][br][bc]);
        }

        float acc[4][4] = {};
        const int NT = KIN / 32;

        #define LOAD1(it, s) {                                                \
            int k0 = (it) * 32;                                               \
            cp16(dAh[s], gAh + k0, 16);                                       \
            cp16(dAl[s], gAl + k0, 16);                                       \
            cp16(dBh[s], g_W1h + (size_t)(k0 + br) * AD + n0 + bc, 16);       \
            cp16(dBl[s], g_W1l + (size_t)(k0 + br) * AD + n0 + bc, 16); }

        PIPE_LOOP(NT, LOAD1, MMA_TILE_KN);
        #undef LOAD1

        #pragma unroll
        for (int nt = 0; nt < 4; nt++) {
            int r0 = m0 + wm * 16 + gid;
            int c0 = n0 + wn * 32 + nt * 8 + 2 * tig;
            float bb0 = b1[c0], bb1 = b1[c0 + 1];
            float v00 = fmaxf(acc[nt][0] + bb0, 0.f), v01 = fmaxf(acc[nt][1] + bb1, 0.f);
            float v10 = fmaxf(acc[nt][2] + bb0, 0.f), v11 = fmaxf(acc[nt][3] + bb1, 0.f);
            __nv_bfloat16 h0, l0, h1, l1;
            split1(v00, h0, l0); split1(v01, h1, l1);
            *(uint32_t*)&g_Xh[(size_t)r0 * AD + c0] = pack2(h0, h1);
            *(uint32_t*)&g_Xl[(size_t)r0 * AD + c0] = pack2(l0, l1);
            split1(v10, h0, l0); split1(v11, h1, l1);
            *(uint32_t*)&g_Xh[(size_t)(r0 + 8) * AD + c0] = pack2(h0, h1);
            *(uint32_t*)&g_Xl[(size_t)(r0 + 8) * AD + c0] = pack2(l0, l1);
        }
    } else {
        if (blockIdx.x >= 7 || blockIdx.y >= 8) return;
        SmA3 Ah = (SmA3)(SB);
        SmA3 Al = (SmA3)(SB + 7680);
        SmA3 Bh = (SmA3)(SB + 15360);
        SmA3 Bl = (SmA3)(SB + 23040);

        int m0 = blockIdx.y * 64, n0 = blockIdx.x * 64;

        LDSM_A_BASE(Ah, Al);
        LDSM_BNK_BASE(Bh, Bl);

        int ar = t >> 2, ac = (t & 3) * 8;
        int rr = n0 + ar;
        int bsz = (rr < NRR) ? 16 : 0;
        const __nv_bfloat16* gRh = g_Rh + (size_t)(rr < NRR ? rr : 0) * DD + ac;
        const __nv_bfloat16* gRl = g_Rl + (size_t)(rr < NRR ? rr : 0) * DD + ac;
        uint32_t dAh[3], dAl[3], dBh[3], dBl[3];
        #pragma unroll
        for (int s = 0; s < 3; s++) {
            dAh[s] = sh_addr(&Ah[s][ar][ac]); dAl[s] = sh_addr(&Al[s][ar][ac]);
            dBh[s] = sh_addr(&Bh[s][ar][ac]); dBl[s] = sh_addr(&Bl[s][ar][ac]);
        }

        float acc[4][4] = {};
        const int NT = DD / 32;

        #define LOADW(it, s) {                                                \
            int k0 = (it) * 32;                                               \
            cp16(dAh[s], g_W2h + (size_t)(m0 + ar) * AD + k0 + ac, 16);       \
            cp16(dAl[s], g_W2l + (size_t)(m0 + ar) * AD + k0 + ac, 16);       \
            cp16(dBh[s], gRh + k0, bsz);                                      \
            cp16(dBl[s], gRl + k0, bsz); }

        PIPE_LOOP(NT, LOADW, MMA_TILE_NK);
        #undef LOADW

        #pragma unroll
        for (int nt = 0; nt < 4; nt++) {
            int r0 = m0 + wm * 16 + gid;
            int c0 = n0 + wn * 32 + nt * 8 + 2 * tig;
            if (c0 < NRR) {
                __nv_bfloat16 h0, l0, h1, l1;
                split1(acc[nt][0], h0, l0); split1(acc[nt][1], h1, l1);
                *(uint32_t*)&g_Wrh[(size_t)r0 * NRR + c0] = pack2(h0, h1);
                *(uint32_t*)&g_Wrl[(size_t)r0 * NRR + c0] = pack2(l0, l1);
                split1(acc[nt][2], h0, l0); split1(acc[nt][3], h1, l1);
                *(uint32_t*)&g_Wrh[(size_t)(r0 + 8) * NRR + c0] = pack2(h0, h1);
                *(uint32_t*)&g_Wrl[(size_t)(r0 + 8) * NRR + c0] = pack2(l0, l1);
            }
        }
    }
}

// ---------------------------------------------------------------------------
// GEMM2 split-K2: Q[z] = X[:, z*256:+256] @ [W2[:,256:512] | Wr].
// ---------------------------------------------------------------------------
__global__ void __launch_bounds__(256)
k_gemm2f()
{
    __shared__ __nv_bfloat16 Ah[3][64][40], Al[3][64][40];
    __shared__ __nv_bfloat16 Bh[3][32][72], Bl[3][32][72];

    GEMM_IDS;
    int m0 = blockIdx.y * 64, n0 = blockIdx.x * 64;
    int koff = blockIdx.z * (AD / 2);
    float* Q = blockIdx.z ? g_Q1 : g_Q0;

    LDSM_A_BASE(Ah, Al);
    LDSM_BKN_BASE(Bh, Bl);

    int ar = t >> 2, ac = (t & 3) * 8;
    int br = t >> 3, bc = (t & 7) * 8;
    int bcol = n0 + bc;
    const __nv_bfloat16* gAh = g_Xh + (size_t)(m0 + ar) * AD + koff + ac;
    const __nv_bfloat16* gAl = g_Xl + (size_t)(m0 + ar) * AD + koff + ac;
    uint32_t dAh[3], dAl[3], dBh[3], dBl[3];
    #pragma unroll
    for (int s = 0; s < 3; s++) {
        dAh[s] = sh_addr(&Ah[s][ar][ac]); dAl[s] = sh_addr(&Al[s][ar][ac]);
        dBh[s] = sh_addr(&Bh[s][br][bc]); dBl[s] = sh_addr(&Bl[s][br][bc]);
    }

    float acc[4][4] = {};
    const int NT = (AD / 2) / 32;

    #define LOAD2(it, s) {                                                    \
        int k0 = (it) * 32;                                                   \
        cp16(dAh[s], gAh + k0, 16);                                           \
        cp16(dAl[s], gAl + k0, 16);                                           \
        int kk = koff + k0 + br;                                              \
        const __nv_bfloat16 *sh_, *sl_; int sz_ = 16;                         \
        if (bcol < DD)       { sh_ = g_W2h + (size_t)kk * AD + DD + bcol;     \
                               sl_ = g_W2l + (size_t)kk * AD + DD + bcol; }   \
        else if (bcol < NF2) { sh_ = g_Wrh + (size_t)kk * NRR + (bcol - DD);  \
                               sl_ = g_Wrl + (size_t)kk * NRR + (bcol - DD); }\
        else                 { sh_ = g_W2h; sl_ = g_W2l; sz_ = 0; }           \
        cp16(dBh[s], sh_, sz_);                                               \
        cp16(dBl[s], sl_, sz_); }

    PIPE_LOOP(NT, LOAD2, MMA_TILE_KN);
    #undef LOAD2

    #pragma unroll
    for (int nt = 0; nt < 4; nt++) {
        int r0 = m0 + wm * 16 + gid;
        int c0 = n0 + wn * 32 + nt * 8 + 2 * tig;
        if (c0 < NF2) {
            *(float2*)&Q[(size_t)r0 * NF2 + c0]       = {acc[nt][0], acc[nt][1]};
            *(float2*)&Q[(size_t)(r0 + 8) * NF2 + c0] = {acc[nt][2], acc[nt][3]};
        }
    }
}

// ---------------------------------------------------------------------------
// k_gather (cp.async staged + TRUE mask-skip): grid (2, 1024), 256 threads.
// 128 actions/block in 8 stages of 16 rows, double-buffered smem; masked
// rows branch around the cp.async entirely (no L1 wavefront) and skip the
// smem read-back (score forced to 0; -HUGE masking makes it irrelevant).
// Staging buffers zeroed once so stale reads are always finite.
// ---------------------------------------------------------------------------
#define GR 16
__global__ void __launch_bounds__(256)
k_gather(const int* __restrict__ e_space,
         const float* __restrict__ mask,
         const float* __restrict__ ent_emb,
         const float* __restrict__ b2)
{
    int b = blockIdx.y;
    int t = threadIdx.x;
    int warp = t >> 5, lane = t & 31;

    __shared__ __align__(16) float x2b[DD];
    __shared__ __align__(16) float stg[2][GR][DD];
    __shared__ int sidx[128];
    __shared__ float smask[128];

    const size_t qb = (size_t)b * NF2;
    x2b[t] = g_Q0[qb + t] + g_Q1[qb + t] + b2[DD + t];
    int abase = blockIdx.x * 128;
    const int base = b * AN;
    if (t < 128) {
        sidx[t]  = e_space[base + abase + t];
        smask[t] = mask[base + abase + t];
    }
    // zero staging so stale reads are finite (NaN-safe)
    float4* zp = reinterpret_cast<float4*>(&stg[0][0][0]);
    #pragma unroll
    for (int i = 0; i < 8; i++) zp[t + i * 256] = make_float4(0.f, 0.f, 0.f, 0.f);
    __syncthreads();

    const float4* xp = reinterpret_cast<const float4*>(x2b);
    float4 xv0 = xp[lane * 2 + 0];
    float4 xv1 = xp[lane * 2 + 1];

    int lrow = t >> 4;
    int lch  = t & 15;
    uint32_t sdst[2] = { sh_addr(&stg[0][lrow][lch * 4]),
                         sh_addr(&stg[1][lrow][lch * 4]) };

    #define GLOAD(s, bf) {                                                    \
        int arow = (s) * GR + lrow;                                           \
        if (smask[arow] != 0.0f) {                                            \
            const float* src = ent_emb + (size_t)sidx[arow] * DD + lch * 4;   \
            _Pragma("unroll")                                                 \
            for (int j = 0; j < 4; j++)                                       \
                cp16(sdst[bf] + (uint32_t)(j * 256), src + j * 64, 16);       \
        } }

    GLOAD(0, 0); cp_commit();
    int bf = 0;
    #pragma unroll 1
    for (int s = 0; s < 8; s++) {
        if (s + 1 < 8) { GLOAD(s + 1, bf ^ 1); }
        cp_commit();
        cp_wait<1>();
        __syncthreads();
        #pragma unroll
        for (int r2 = 0; r2 < 2; r2++) {
            int row = warp * 2 + r2;
            int arow = s * GR + row;
            float sv = 0.0f;
            if (smask[arow] != 0.0f) {
                const float4* rp = reinterpret_cast<const float4*>(&stg[bf][row][0]);
                float4 v0 = rp[lane * 2 + 0];
                float4 v1 = rp[lane * 2 + 1];
                sv = v0.x * xv0.x + v0.y * xv0.y + v0.z * xv0.z + v0.w * xv0.w
                   + v1.x * xv1.x + v1.y * xv1.y + v1.z * xv1.z + v1.w * xv1.w;
                #pragma unroll
                for (int o = 16; o > 0; o >>= 1) sv += __shfl_xor_sync(0xFFFFFFFFu, sv, o);
            }
            if (lane == 0) g_S[base + abase + arow] = sv;
        }
        __syncthreads();
        bf ^= 1;
    }
    #undef GLOAD
}

// ---------------------------------------------------------------------------
// k_softmax: relation term + mask, softmax, entropy.  Grid 1024, 256 thr.
// ---------------------------------------------------------------------------
__global__ void __launch_bounds__(256)
k_softmax(const int*   __restrict__ r_space,
          const float* __restrict__ mask,
          float* __restrict__ dist,
          float* __restrict__ entropy)
{
    int b = blockIdx.x;
    int t = threadIdx.x;
    int warp = t >> 5, lane = t & 31;

    __shared__ float rp[NRR];
    __shared__ float red[8];

    const size_t qb = (size_t)b * NF2;
    for (int i = t; i < NRR; i += 256)
        rp[i] = g_Q0[qb + DD + i] + g_Q1[qb + DD + i] + g_br[i];
    __syncthreads();

    int ir = r_space[b * AN + t];
    float m = mask[b * AN + t];
    float s = g_S[b * AN + t] + rp[ir] - (1.0f - m) * HUGEV;

    float mx = s;
    #pragma unroll
    for (int o = 16; o > 0; o >>= 1) mx = fmaxf(mx, __shfl_xor_sync(0xFFFFFFFFu, mx, o));
    if (lane == 0) red[warp] = mx;
    __syncthreads();
    if (t < 8) {
        float v = red[t];
        #pragma unroll
        for (int o = 4; o > 0; o >>= 1) v = fmaxf(v, __shfl_xor_sync(0xFFu, v, o));
        if (t == 0) red[0] = v;
    }
    __syncthreads();
    mx = red[0];

    float ex = expf(s - mx);

    float sm = ex;
    #pragma unroll
    for (int o = 16; o > 0; o >>= 1) sm += __shfl_xor_sync(0xFFFFFFFFu, sm, o);
    __syncthreads();
    if (lane == 0) red[warp] = sm;
    __syncthreads();
    if (t < 8) {
        float v = red[t];
        #pragma unroll
        for (int o = 4; o > 0; o >>= 1) v += __shfl_xor_sync(0xFFu, v, o);
        if (t == 0) red[0] = v;
    }
    __syncthreads();
    float total = red[0];

    float p = ex / total;
    dist[(size_t)b * AN + t] = p;

    float term = p * logf(fmaxf(p, 1e-20f));
    float es = term;
    #pragma unroll
    for (int o = 16; o > 0; o >>= 1) es += __shfl_xor_sync(0xFFFFFFFFu, es, o);
    __syncthreads();
    if (lane == 0) red[warp] = es;
    __syncthreads();
    if (t < 8) {
        float v = red[t];
        #pragma unroll
        for (int o = 4; o > 0; o >>= 1) v += __shfl_xor_sync(0xFFu, v, o);
        if (t == 0) entropy[b] = -v;
    }
}

// ---------------------------------------------------------------------------
extern "C" void kernel_launch(void* const* d_in, const int* in_sizes, int n_in,
                              void* d_out, int out_size)
{
    const int*   e        = (const int*)  d_in[0];
    const int*   q        = (const int*)  d_in[1];
    const float* hstate   = (const float*)d_in[2];
    const int*   r_space  = (const int*)  d_in[3];
    const int*   e_space  = (const int*)  d_in[4];
    const float* amask    = (const float*)d_in[5];
    const float* ent_emb  = (const float*)d_in[6];
    const float* rel_emb  = (const float*)d_in[7];
    const float* W1       = (const float*)d_in[8];
    const float* b1       = (const float*)d_in[9];
    const float* W2       = (const float*)d_in[10];
    const float* b2       = (const float*)d_in[11];

    float* dist    = (float*)d_out;
    float* entropy = (float*)d_out + (size_t)BB * AN;

    k_prep<<<UB + BR_B, 256>>>(e, q, hstate, ent_emb, rel_emb, W1, W2, b2);

    dim3 g1(8, 16, 2);                          // z=0 gemm1, z=1 wr
    k_wrg1<<<g1, 256>>>(b1);

    dim3 g2((NF2 + 63) / 64, BB / 64, 2);       // (11, 16, 2) = 352
    k_gemm2f<<<g2, 256>>>();

    dim3 gg(2, BB);                             // (2, 1024)
    k_gather<<<gg, 256>>>(e_space, amask, ent_emb, b2);

    k_softmax<<<BB, 256>>>(r_space, amask, dist, entropy);
}